// round 3
// baseline (speedup 1.0000x reference)
#include <cuda_runtime.h>
#include <math.h>

#define T_ 1024
#define S_ 1024
#define B_ 8
#define E_ 768
#define H_ 12
#define D_ 64
#define TT 16
#define NTILES (T_/TT)
#define WROW 1028   // padded wbuf/arcs row stride (floats); 4112B == 16 mod 128

// ---------------- scratch (device globals: allocation-free) ----------------
__device__ float g_Q[T_*B_*E_];          // [T,B,E]
__device__ float g_K[B_*H_*S_*D_];       // [B,H,S,D]
__device__ float g_V[B_*H_*S_*D_];       // [B,H,S,D]
__device__ float g_attn[T_*B_*E_];       // [T,B,E]
__device__ float g_losspart[NTILES*B_];  // per-tile partial BCE sums

// ---------------- SGEMM (NT), double-buffered: C = (A @ W^T + bias) * scale ----
// A: [M,768] row-major, W: [N,768] row-major (dot over contiguous K).
// grid (M/64, N/64), block 256. bhsd=0: C[r*768 + e]; bhsd=1: C[((b*H + head)*s + s)*64 + d]
__global__ __launch_bounds__(256) void sgemm_nt(
    const float* __restrict__ A, const float* __restrict__ W,
    const float* __restrict__ bias, float* __restrict__ C,
    float scale, int bhsd)
{
    __shared__ float As[2][16][68];
    __shared__ float Ws[2][16][68];
    const int tid = threadIdx.x;
    const int bm = blockIdx.x, bn = blockIdx.y;
    const int ti = tid & 15, tj = tid >> 4;
    const int lrow = tid >> 2, lk = (tid & 3) * 4;
    const float* Ar = A + (bm*64 + lrow)*768 + lk;
    const float* Wr = W + (bn*64 + lrow)*768 + lk;

    float acc[4][4];
#pragma unroll
    for (int r = 0; r < 4; r++)
#pragma unroll
        for (int c = 0; c < 4; c++) acc[r][c] = 0.f;

    // prologue: load tile 0
    {
        float4 a4 = *(const float4*)(Ar);
        float4 w4 = *(const float4*)(Wr);
        As[0][lk+0][lrow] = a4.x; As[0][lk+1][lrow] = a4.y;
        As[0][lk+2][lrow] = a4.z; As[0][lk+3][lrow] = a4.w;
        Ws[0][lk+0][lrow] = w4.x; Ws[0][lk+1][lrow] = w4.y;
        Ws[0][lk+2][lrow] = w4.z; Ws[0][lk+3][lrow] = w4.w;
    }
    __syncthreads();

    int buf = 0;
    for (int k0 = 0; k0 < 768; k0 += 16) {
        float4 a4n, w4n;
        bool more = (k0 + 16) < 768;
        if (more) {
            a4n = *(const float4*)(Ar + k0 + 16);
            w4n = *(const float4*)(Wr + k0 + 16);
        }
#pragma unroll
        for (int kk = 0; kk < 16; kk++) {
            float4 av = *(const float4*)&As[buf][kk][ti*4];
            float4 wv = *(const float4*)&Ws[buf][kk][tj*4];
            acc[0][0] += av.x*wv.x; acc[0][1] += av.x*wv.y; acc[0][2] += av.x*wv.z; acc[0][3] += av.x*wv.w;
            acc[1][0] += av.y*wv.x; acc[1][1] += av.y*wv.y; acc[1][2] += av.y*wv.z; acc[1][3] += av.y*wv.w;
            acc[2][0] += av.z*wv.x; acc[2][1] += av.z*wv.y; acc[2][2] += av.z*wv.z; acc[2][3] += av.z*wv.w;
            acc[3][0] += av.w*wv.x; acc[3][1] += av.w*wv.y; acc[3][2] += av.w*wv.z; acc[3][3] += av.w*wv.w;
        }
        if (more) {
            int nb = buf ^ 1;
            As[nb][lk+0][lrow] = a4n.x; As[nb][lk+1][lrow] = a4n.y;
            As[nb][lk+2][lrow] = a4n.z; As[nb][lk+3][lrow] = a4n.w;
            Ws[nb][lk+0][lrow] = w4n.x; Ws[nb][lk+1][lrow] = w4n.y;
            Ws[nb][lk+2][lrow] = w4n.z; Ws[nb][lk+3][lrow] = w4n.w;
        }
        __syncthreads();
        buf ^= 1;
    }

    float4 b4 = *(const float4*)&bias[bn*64 + tj*4];
#pragma unroll
    for (int r = 0; r < 4; r++) {
        int grow = bm*64 + ti*4 + r;
        float4 v;
        v.x = (acc[r][0] + b4.x) * scale;
        v.y = (acc[r][1] + b4.y) * scale;
        v.z = (acc[r][2] + b4.z) * scale;
        v.w = (acc[r][3] + b4.w) * scale;
        if (!bhsd) {
            *(float4*)&C[grow*768 + bn*64 + tj*4] = v;
        } else {
            int seq = grow >> 3;          // row = s*B + b
            int bb  = grow & 7;
            *(float4*)&C[((bb*H_ + bn)*S_ + seq)*64 + tj*4] = v;
        }
    }
}

// ---------------- fused attention + head-max + BCE ----------------
// grid (T/TT, B), block 256, dynamic smem 205568 B.
__global__ __launch_bounds__(256) void attn_kernel(
    const float* __restrict__ Q, const float* __restrict__ K, const float* __restrict__ V,
    const float* __restrict__ amask, const unsigned char* __restrict__ pmask,
    const int* __restrict__ trel, float* __restrict__ attn_out, float* __restrict__ losspart)
{
    extern __shared__ float sm[];
    float* kvs  = sm;                    // 256*68 floats (K/V chunk, padded rows of 17 float4)
    float* wbuf = sm + 256*68;           // 16*WROW (logits -> weights)
    float* arcs = wbuf + 16*WROW;        // 16*WROW (running head-max)
    float* qh   = arcs + 16*WROW;        // 16*68 (per-head Q tile, padded)
    float4* kvs4 = (float4*)kvs;
    float4* qh4  = (float4*)qh;

    const int t = threadIdx.x;
    const int t0 = blockIdx.x * TT;
    const int b  = blockIdx.y;
    const int lane = t & 31, warp = t >> 5;
    const int ig = t >> 6, sg = t & 63;          // logits: 4 i-groups x 64 s-lanes (strided c)
    const int oig = t >> 6;                       // O-phase: 4 i-groups
    const int oks = (t >> 4) & 3;                 //          4 split-k slices
    const int odg = t & 15;                       //          16 d-float4
    const int li = t >> 4, ldq = t & 15;          // loads: 16 rows x 16 quads

    for (int idx = t; idx < 16*WROW; idx += 256) arcs[idx] = 0.f;

    for (int h = 0; h < H_; h++) {
        __syncthreads();  // protect kvs/qh from previous head's readers
        // per-head Q tile [16][64]
        qh4[li*17 + ldq] = *(const float4*)&Q[((t0+li)*B_ + b)*E_ + h*D_ + ldq*4];

        const float* Kh = K + (size_t)((b*H_ + h)*S_) * D_;
        // ---- logits: 4 chunks of 256 s ----
        for (int c0 = 0; c0 < 4; c0++) {
            int s0 = c0 * 256;
            if (c0) __syncthreads();
#pragma unroll
            for (int j = 0; j < 16; j++) {
                int idx = t + 256*j;
                int row = idx >> 4, c4 = idx & 15;
                kvs4[row*17 + c4] = *(const float4*)&Kh[(s0+row)*64 + c4*4];
            }
            __syncthreads();
            float acc[4][4];
#pragma unroll
            for (int r = 0; r < 4; r++)
#pragma unroll
                for (int c = 0; c < 4; c++) acc[r][c] = 0.f;
#pragma unroll
            for (int kk = 0; kk < 16; kk++) {
                float4 qv0 = qh4[(ig*4+0)*17 + kk];
                float4 qv1 = qh4[(ig*4+1)*17 + kk];
                float4 qv2 = qh4[(ig*4+2)*17 + kk];
                float4 qv3 = qh4[(ig*4+3)*17 + kk];
#pragma unroll
                for (int c = 0; c < 4; c++) {
                    float4 kv = kvs4[(sg + 64*c)*17 + kk];   // lane stride = 1 row: conflict-free
                    acc[0][c] += qv0.x*kv.x + qv0.y*kv.y + qv0.z*kv.z + qv0.w*kv.w;
                    acc[1][c] += qv1.x*kv.x + qv1.y*kv.y + qv1.z*kv.z + qv1.w*kv.w;
                    acc[2][c] += qv2.x*kv.x + qv2.y*kv.y + qv2.z*kv.z + qv2.w*kv.w;
                    acc[3][c] += qv3.x*kv.x + qv3.y*kv.y + qv3.z*kv.z + qv3.w*kv.w;
                }
            }
#pragma unroll
            for (int c = 0; c < 4; c++) {
                int s = s0 + sg + 64*c;
                bool pm = (pmask[b*S_ + s] != 0);
#pragma unroll
                for (int r = 0; r < 4; r++) {
                    int i = ig*4 + r;
                    float l = acc[r][c] + amask[(size_t)(t0+i)*S_ + s];
                    wbuf[i*WROW + s] = pm ? -INFINITY : l;
                }
            }
        }
        __syncthreads();

        // ---- softmax per row (warp handles 2 rows) + arc-max update ----
        for (int rr = 0; rr < 2; rr++) {
            int i = warp*2 + rr;
            float* wrow = wbuf + i*WROW;
            float* arow = arcs + i*WROW;
            float m = -INFINITY;
            for (int s = lane; s < 1024; s += 32) m = fmaxf(m, wrow[s]);
#pragma unroll
            for (int off = 16; off; off >>= 1) m = fmaxf(m, __shfl_xor_sync(0xffffffffu, m, off));
            float ssum = 0.f;
            for (int s = lane; s < 1024; s += 32) {
                float e = __expf(wrow[s] - m);
                wrow[s] = e;
                ssum += e;
            }
#pragma unroll
            for (int off = 16; off; off >>= 1) ssum += __shfl_xor_sync(0xffffffffu, ssum, off);
            float inv = 1.f / ssum;
            for (int s = lane; s < 1024; s += 32) {
                float wv = wrow[s] * inv;
                wrow[s] = wv;
                arow[s] = fmaxf(arow[s], wv);
            }
        }
        __syncthreads();

        // ---- O = W @ V : 4 chunks of 256 s, micro 4i x 4d, split-k 4 ----
        const float* Vh = V + (size_t)((b*H_ + h)*S_) * D_;
        float4 oacc[4];
#pragma unroll
        for (int r = 0; r < 4; r++) oacc[r] = make_float4(0.f, 0.f, 0.f, 0.f);

        for (int c0 = 0; c0 < 4; c0++) {
            int s0 = c0 * 256;
            if (c0) __syncthreads();
#pragma unroll
            for (int j = 0; j < 16; j++) {
                int idx = t + 256*j;
                int row = idx >> 4, c4 = idx & 15;
                kvs4[row*17 + c4] = *(const float4*)&Vh[(s0+row)*64 + c4*4];
            }
            __syncthreads();
            int sl0 = oks * 64;   // this thread's k-slice within the chunk
#pragma unroll 4
            for (int g = 0; g < 16; g++) {
                float wv[4][4];
#pragma unroll
                for (int r = 0; r < 4; r++) {
                    float4 w4 = *(const float4*)&wbuf[(oig*4+r)*WROW + s0 + sl0 + g*4];
                    wv[r][0] = w4.x; wv[r][1] = w4.y; wv[r][2] = w4.z; wv[r][3] = w4.w;
                }
#pragma unroll
                for (int j = 0; j < 4; j++) {
                    float4 v = kvs4[(sl0 + g*4 + j)*17 + odg];
#pragma unroll
                    for (int r = 0; r < 4; r++) {
                        oacc[r].x += wv[r][j]*v.x;
                        oacc[r].y += wv[r][j]*v.y;
                        oacc[r].z += wv[r][j]*v.z;
                        oacc[r].w += wv[r][j]*v.w;
                    }
                }
            }
        }
        // split-k reduction via smem (reuse kvs)
        __syncthreads();
        float4* red4 = (float4*)kvs;
#pragma unroll
        for (int r = 0; r < 4; r++) red4[t*4 + r] = oacc[r];
        __syncthreads();
        if (oks == 0) {
#pragma unroll
            for (int r = 0; r < 4; r++) {
                float4 o = oacc[r];
#pragma unroll
                for (int ks = 1; ks < 4; ks++) {
                    int peer = oig*64 + ks*16 + odg;
                    float4 p = red4[peer*4 + r];
                    o.x += p.x; o.y += p.y; o.z += p.z; o.w += p.w;
                }
                *(float4*)&attn_out[((t0 + oig*4 + r)*B_ + b)*E_ + h*D_ + odg*4] = o;
            }
        }
    }
    __syncthreads();

    // ---- BCE over head-max weights ----
    float lsum = 0.f;
    for (int k = 0; k < 64; k++) {
        int idx = t + 256*k;
        int i = idx >> 10, s = idx & 1023;
        int rel = trel[(size_t)((t0+i)*B_ + b)*S_ + s];
        if (rel != 0) {
            float p = fminf(arcs[i*WROW + s], 1.0f);
            float term = (rel != 2) ? logf(p) : log1pf(-p);
            lsum -= fmaxf(term, -100.f);
        }
    }
    float* red = kvs;  // reuse
    red[t] = lsum;
    __syncthreads();
    for (int off = 128; off; off >>= 1) {
        if (t < off) red[t] += red[t + off];
        __syncthreads();
    }
    if (t == 0) losspart[blockIdx.x * B_ + b] = red[0];
}

// ---------------- deterministic loss finalize ----------------
__global__ void finalize_kernel(const float* __restrict__ lp,
                                const float* __restrict__ strat,
                                float* __restrict__ out)
{
    int b = threadIdx.x;
    if (b < B_) {
        float s = 0.f;
        for (int k = 0; k < NTILES; k++) s += lp[k*B_ + b];
        out[b] = s * strat[b];
    }
}

// ---------------- launch ----------------
extern "C" void kernel_launch(void* const* d_in, const int* in_sizes, int n_in,
                              void* d_out, int out_size)
{
    const float* outs = nullptr; const float* gstate = nullptr;
    const unsigned char* pmask = nullptr; const float* amask = nullptr;
    const float* strat = nullptr; const int* trel = nullptr;
    const float* Win = nullptr; const float* b_in = nullptr;
    const float* Wout = nullptr; const float* b_out = nullptr;
    for (int i = 0; i < n_in; i++) {
        long n = in_sizes[i];
        if (n == (long)T_*B_*E_) { if (!outs) outs = (const float*)d_in[i]; else if (!gstate) gstate = (const float*)d_in[i]; }
        else if (n == (long)B_*S_)      pmask = (const unsigned char*)d_in[i];
        else if (n == (long)T_*S_)      amask = (const float*)d_in[i];
        else if (n == (long)B_)         strat = (const float*)d_in[i];
        else if (n == (long)T_*B_*S_)   trel  = (const int*)d_in[i];
        else if (n == (long)3*E_*E_)    Win   = (const float*)d_in[i];
        else if (n == (long)3*E_)       b_in  = (const float*)d_in[i];
        else if (n == (long)E_*E_)      Wout  = (const float*)d_in[i];
        else if (n == (long)E_)         b_out = (const float*)d_in[i];
    }
    float* out = (float*)d_out;

    float *Qp, *Kp, *Vp, *Ap, *Lp;
    cudaGetSymbolAddress((void**)&Qp, g_Q);
    cudaGetSymbolAddress((void**)&Kp, g_K);
    cudaGetSymbolAddress((void**)&Vp, g_V);
    cudaGetSymbolAddress((void**)&Ap, g_attn);
    cudaGetSymbolAddress((void**)&Lp, g_losspart);

    // outs passthrough (output layout: [arc_loss(8) | outs(T*B*E) | x(T*B*E)])
    cudaMemcpyAsync(out + B_, outs, sizeof(float)*(size_t)T_*B_*E_,
                    cudaMemcpyDeviceToDevice);

    dim3 gg(T_*B_/64, E_/64);   // (128, 12)
    sgemm_nt<<<gg, 256>>>(outs,   Win,            b_in,        Qp, 0.125f, 0);
    sgemm_nt<<<gg, 256>>>(gstate, Win +   E_*E_,  b_in +   E_, Kp, 1.0f,   1);
    sgemm_nt<<<gg, 256>>>(gstate, Win + 2*E_*E_,  b_in + 2*E_, Vp, 1.0f,   1);

    const int ATTN_SMEM = (256*68 + 16*WROW + 16*WROW + 16*68) * 4;  // 205568 B
    cudaFuncSetAttribute(attn_kernel, cudaFuncAttributeMaxDynamicSharedMemorySize, ATTN_SMEM);
    attn_kernel<<<dim3(NTILES, B_), 256, ATTN_SMEM>>>(Qp, Kp, Vp, amask, pmask, trel, Ap, Lp);

    sgemm_nt<<<gg, 256>>>(Ap, Wout, b_out, out + B_ + (size_t)T_*B_*E_, 1.0f, 0);

    finalize_kernel<<<1, 32>>>(Lp, strat, out);
}

// round 7
// speedup vs baseline: 1.3148x; 1.3148x over previous
#include <cuda_runtime.h>
#include <cuda_bf16.h>
#include <math.h>
#include <stdint.h>

#define T_ 1024
#define S_ 1024
#define B_ 8
#define E_ 768
#define H_ 12
#define D_ 64
#define TT 16
#define NTILES (T_/TT)
#define WROW 1028   // padded wbuf/arcs row stride (floats)

// ---------------- scratch (device globals: allocation-free) ----------------
__device__ float g_Q[T_*B_*E_];          // [T,B,E] (row = t*B+b)
__device__ float g_K[B_*H_*S_*D_];       // [B,H,S,D]
__device__ float g_V[B_*H_*S_*D_];       // [B,H,S,D]
__device__ float g_attn[T_*B_*E_];       // [T,B,E]
__device__ float g_losspart[NTILES*B_];  // per-tile partial BCE sums

// split-bf16 operands
__device__ __nv_bfloat16 g_oh[T_*B_*E_], g_ol[T_*B_*E_];   // outs hi/lo
__device__ __nv_bfloat16 g_gh[S_*B_*E_], g_gl[S_*B_*E_];   // graph_state hi/lo
__device__ __nv_bfloat16 g_th[T_*B_*E_], g_tl[T_*B_*E_];   // attn-out hi/lo
__device__ __nv_bfloat16 g_Wh[4*E_*E_],  g_Wl[4*E_*E_];    // [Win(3E) | Wout(E)] x E

// ================= helpers =============
__device__ __forceinline__ uint32_t smem_to_u32(const void* p) {
    uint32_t a;
    asm("{ .reg .u64 tmp; cvta.to.shared.u64 tmp, %1; cvt.u32.u64 %0, tmp; }" : "=r"(a) : "l"(p));
    return a;
}
__device__ __forceinline__ void ldsm4(uint32_t* r, uint32_t addr) {
    asm volatile("ldmatrix.sync.aligned.m8n8.x4.shared.b16 {%0,%1,%2,%3}, [%4];"
        : "=r"(r[0]), "=r"(r[1]), "=r"(r[2]), "=r"(r[3]) : "r"(addr));
}
__device__ __forceinline__ void mma16816(float* d, const uint32_t* a, const uint32_t* b) {
    asm volatile("mma.sync.aligned.m16n8k16.row.col.f32.bf16.bf16.f32 "
        "{%0,%1,%2,%3}, {%4,%5,%6,%7}, {%8,%9}, {%0,%1,%2,%3};"
        : "+f"(d[0]), "+f"(d[1]), "+f"(d[2]), "+f"(d[3])
        : "r"(a[0]), "r"(a[1]), "r"(a[2]), "r"(a[3]), "r"(b[0]), "r"(b[1]));
}

// ================ fp32 -> (bf16 hi, bf16 lo) split conversion ================
__global__ __launch_bounds__(256) void cvt_split(
    const float* __restrict__ x, __nv_bfloat16* __restrict__ hi,
    __nv_bfloat16* __restrict__ lo, int n4)
{
    int i = blockIdx.x * 256 + threadIdx.x;
    if (i >= n4) return;
    float4 v = ((const float4*)x)[i];
    __nv_bfloat16 h0 = __float2bfloat16(v.x), h1 = __float2bfloat16(v.y);
    __nv_bfloat16 h2 = __float2bfloat16(v.z), h3 = __float2bfloat16(v.w);
    __nv_bfloat16 l0 = __float2bfloat16(v.x - __bfloat162float(h0));
    __nv_bfloat16 l1 = __float2bfloat16(v.y - __bfloat162float(h1));
    __nv_bfloat16 l2 = __float2bfloat16(v.z - __bfloat162float(h2));
    __nv_bfloat16 l3 = __float2bfloat16(v.w - __bfloat162float(h3));
    ((__nv_bfloat162*)hi)[2*i]   = __nv_bfloat162(h0, h1);
    ((__nv_bfloat162*)hi)[2*i+1] = __nv_bfloat162(h2, h3);
    ((__nv_bfloat162*)lo)[2*i]   = __nv_bfloat162(l0, l1);
    ((__nv_bfloat162*)lo)[2*i+1] = __nv_bfloat162(l2, l3);
}

// ================ warp-MMA split-bf16 GEMM =================
// C[8192,768] = (A @ W^T + bias) * scale ; A,W split hi/lo bf16, K=768.
// grid (64, 12), block 256 (8 warps), dyn smem 61440 B.
// Block tile 128(M) x 64(N); warp tile 32x32; k-chunk 32, double-buffered.
#define SP 40                 // padded smem row stride (bf16)
#define AH_OFF 0
#define AL_OFF (128*SP)
#define WH_OFF (2*128*SP)
#define WL_OFF (2*128*SP + 64*SP)
#define STAGE_ELEMS (2*128*SP + 2*64*SP)   // 15360 bf16 per stage

__global__ __launch_bounds__(256) void mma_gemm(
    const __nv_bfloat16* __restrict__ Ah, const __nv_bfloat16* __restrict__ Al,
    const __nv_bfloat16* __restrict__ Wh, const __nv_bfloat16* __restrict__ Wl,
    const float* __restrict__ bias, float* __restrict__ C, float scale, int bhsd)
{
    extern __shared__ __nv_bfloat16 smb[];
    const int t = threadIdx.x, lane = t & 31, w = t >> 5;
    const int bm = blockIdx.x, bn = blockIdx.y;
    const int wm = w & 3, wn = w >> 2;      // warp grid 4(m) x 2(n)
    const uint32_t sbase = smem_to_u32(smb);

    float acc[2][4][4];
#pragma unroll
    for (int mt = 0; mt < 2; mt++)
#pragma unroll
        for (int nt = 0; nt < 4; nt++)
#pragma unroll
            for (int k = 0; k < 4; k++) acc[mt][nt][k] = 0.f;

    // load indices: A 128 rows x 4 quads (2 per thread), W 64 rows x 4 quads (1 per thread)
    const int ar0 = t >> 2, aq = t & 3;          // rows 0..63
    const int ar1 = ar0 + 64;                    // rows 64..127
    const int wr = t >> 2, wq = t & 3;           // rows 0..63

    const __nv_bfloat16* Abase  = Ah + (size_t)(bm*128)*768;
    const __nv_bfloat16* AbaseL = Al + (size_t)(bm*128)*768;
    const __nv_bfloat16* Wbase  = Wh + (size_t)(bn*64)*768;
    const __nv_bfloat16* WbaseL = Wl + (size_t)(bn*64)*768;

    float4 rAh0, rAh1, rAl0, rAl1, rWh, rWl;
    // prologue: chunk 0 -> regs -> stage 0
    rAh0 = *(const float4*)(Abase  + (size_t)ar0*768 + aq*8);
    rAh1 = *(const float4*)(Abase  + (size_t)ar1*768 + aq*8);
    rAl0 = *(const float4*)(AbaseL + (size_t)ar0*768 + aq*8);
    rAl1 = *(const float4*)(AbaseL + (size_t)ar1*768 + aq*8);
    rWh  = *(const float4*)(Wbase  + (size_t)wr*768 + wq*8);
    rWl  = *(const float4*)(WbaseL + (size_t)wr*768 + wq*8);
    {
        __nv_bfloat16* st = smb;
        *(float4*)(st + AH_OFF + ar0*SP + aq*8) = rAh0;
        *(float4*)(st + AH_OFF + ar1*SP + aq*8) = rAh1;
        *(float4*)(st + AL_OFF + ar0*SP + aq*8) = rAl0;
        *(float4*)(st + AL_OFF + ar1*SP + aq*8) = rAl1;
        *(float4*)(st + WH_OFF + wr*SP + wq*8) = rWh;
        *(float4*)(st + WL_OFF + wr*SP + wq*8) = rWl;
    }
    __syncthreads();

    const int arow = lane & 15;
    const int acolb = (lane >> 4) * 8;
    const int brow = (lane & 7) + ((lane >> 4) * 8);
    const int bcolb = ((lane >> 3) & 1) * 8;

    for (int c = 0; c < 24; c++) {
        // prefetch next chunk to regs
        if (c < 23) {
            int k0 = (c + 1) * 32;
            rAh0 = *(const float4*)(Abase  + (size_t)ar0*768 + k0 + aq*8);
            rAh1 = *(const float4*)(Abase  + (size_t)ar1*768 + k0 + aq*8);
            rAl0 = *(const float4*)(AbaseL + (size_t)ar0*768 + k0 + aq*8);
            rAl1 = *(const float4*)(AbaseL + (size_t)ar1*768 + k0 + aq*8);
            rWh  = *(const float4*)(Wbase  + (size_t)wr*768 + k0 + wq*8);
            rWl  = *(const float4*)(WbaseL + (size_t)wr*768 + k0 + wq*8);
        }
        // compute current chunk from stage c&1
        const uint32_t st = sbase + (uint32_t)((c & 1) * STAGE_ELEMS) * 2;
#pragma unroll
        for (int kk = 0; kk < 2; kk++) {
            uint32_t fa_h[2][4], fa_l[2][4], fb_h[2][4], fb_l[2][4];
            int acol = acolb + kk*16;
            int bcol = bcolb + kk*16;
#pragma unroll
            for (int mt = 0; mt < 2; mt++) {
                int r = wm*32 + mt*16 + arow;
                ldsm4(fa_h[mt], st + (uint32_t)(AH_OFF + r*SP + acol) * 2);
                ldsm4(fa_l[mt], st + (uint32_t)(AL_OFF + r*SP + acol) * 2);
            }
#pragma unroll
            for (int p = 0; p < 2; p++) {
                int r = wn*32 + p*16 + brow;
                ldsm4(fb_h[p], st + (uint32_t)(WH_OFF + r*SP + bcol) * 2);
                ldsm4(fb_l[p], st + (uint32_t)(WL_OFF + r*SP + bcol) * 2);
            }
#pragma unroll
            for (int mt = 0; mt < 2; mt++)
#pragma unroll
                for (int p = 0; p < 2; p++)
#pragma unroll
                    for (int hf = 0; hf < 2; hf++) {
                        int nt = p*2 + hf;
                        mma16816(acc[mt][nt], fa_h[mt], &fb_h[p][hf*2]);
                        mma16816(acc[mt][nt], fa_h[mt], &fb_l[p][hf*2]);
                        mma16816(acc[mt][nt], fa_l[mt], &fb_h[p][hf*2]);
                    }
        }
        // store prefetched regs into the other stage
        if (c < 23) {
            __nv_bfloat16* stn = smb + ((c + 1) & 1) * STAGE_ELEMS;
            *(float4*)(stn + AH_OFF + ar0*SP + aq*8) = rAh0;
            *(float4*)(stn + AH_OFF + ar1*SP + aq*8) = rAh1;
            *(float4*)(stn + AL_OFF + ar0*SP + aq*8) = rAl0;
            *(float4*)(stn + AL_OFF + ar1*SP + aq*8) = rAl1;
            *(float4*)(stn + WH_OFF + wr*SP + wq*8) = rWh;
            *(float4*)(stn + WL_OFF + wr*SP + wq*8) = rWl;
        }
        __syncthreads();
    }

    // epilogue: direct stores with bias + scale (+ bhsd remap)
    const int gid = lane >> 2, tig = lane & 3;
#pragma unroll
    for (int mt = 0; mt < 2; mt++) {
#pragma unroll
        for (int nt = 0; nt < 4; nt++) {
            int colL = wn*32 + nt*8 + tig*2;
            float b0 = bias[bn*64 + colL], b1 = bias[bn*64 + colL + 1];
#pragma unroll
            for (int hrow = 0; hrow < 2; hrow++) {
                int rg = bm*128 + wm*32 + mt*16 + gid + hrow*8;
                float2 v;
                v.x = (acc[mt][nt][hrow*2+0] + b0) * scale;
                v.y = (acc[mt][nt][hrow*2+1] + b1) * scale;
                if (!bhsd) {
                    *(float2*)&C[(size_t)rg*768 + bn*64 + colL] = v;
                } else {
                    int s = rg >> 3, b = rg & 7;   // row = s*B + b
                    *(float2*)&C[(size_t)((b*H_ + bn)*S_ + s)*64 + colL] = v;
                }
            }
        }
    }
}

// ---------------- fused attention + head-max + BCE ----------------
__global__ __launch_bounds__(256) void attn_kernel(
    const float* __restrict__ Q, const float* __restrict__ K, const float* __restrict__ V,
    const float* __restrict__ amask, const unsigned char* __restrict__ pmask,
    const int* __restrict__ trel, float* __restrict__ attn_out, float* __restrict__ losspart)
{
    extern __shared__ float sm[];
    float* kvs  = sm;                    // 256*68
    float* wbuf = sm + 256*68;           // 16*WROW
    float* arcs = wbuf + 16*WROW;        // 16*WROW
    float* qh   = arcs + 16*WROW;        // 16*68
    float4* kvs4 = (float4*)kvs;
    float4* qh4  = (float4*)qh;

    const int t = threadIdx.x;
    const int t0 = blockIdx.x * TT;
    const int b  = blockIdx.y;
    const int lane = t & 31, warp = t >> 5;
    const int ig = t >> 6, sg = t & 63;
    const int oig = t >> 6;
    const int oks = (t >> 4) & 3;
    const int odg = t & 15;
    const int li = t >> 4, ldq = t & 15;

    for (int idx = t; idx < 16*WROW; idx += 256) arcs[idx] = 0.f;

    for (int h = 0; h < H_; h++) {
        __syncthreads();
        qh4[li*17 + ldq] = *(const float4*)&Q[((t0+li)*B_ + b)*E_ + h*D_ + ldq*4];

        const float* Kh = K + (size_t)((b*H_ + h)*S_) * D_;
        for (int c0 = 0; c0 < 4; c0++) {
            int s0 = c0 * 256;
            if (c0) __syncthreads();
#pragma unroll
            for (int j = 0; j < 16; j++) {
                int idx = t + 256*j;
                int row = idx >> 4, c4 = idx & 15;
                kvs4[row*17 + c4] = *(const float4*)&Kh[(s0+row)*64 + c4*4];
            }
            __syncthreads();
            float acc[4][4];
#pragma unroll
            for (int r = 0; r < 4; r++)
#pragma unroll
                for (int c = 0; c < 4; c++) acc[r][c] = 0.f;
#pragma unroll
            for (int kk = 0; kk < 16; kk++) {
                float4 qv0 = qh4[(ig*4+0)*17 + kk];
                float4 qv1 = qh4[(ig*4+1)*17 + kk];
                float4 qv2 = qh4[(ig*4+2)*17 + kk];
                float4 qv3 = qh4[(ig*4+3)*17 + kk];
#pragma unroll
                for (int c = 0; c < 4; c++) {
                    float4 kv = kvs4[(sg + 64*c)*17 + kk];
                    acc[0][c] += qv0.x*kv.x + qv0.y*kv.y + qv0.z*kv.z + qv0.w*kv.w;
                    acc[1][c] += qv1.x*kv.x + qv1.y*kv.y + qv1.z*kv.z + qv1.w*kv.w;
                    acc[2][c] += qv2.x*kv.x + qv2.y*kv.y + qv2.z*kv.z + qv2.w*kv.w;
                    acc[3][c] += qv3.x*kv.x + qv3.y*kv.y + qv3.z*kv.z + qv3.w*kv.w;
                }
            }
#pragma unroll
            for (int c = 0; c < 4; c++) {
                int s = s0 + sg + 64*c;
                bool pm = (pmask[b*S_ + s] != 0);
#pragma unroll
                for (int r = 0; r < 4; r++) {
                    int i = ig*4 + r;
                    float l = acc[r][c] + amask[(size_t)(t0+i)*S_ + s];
                    wbuf[i*WROW + s] = pm ? -INFINITY : l;
                }
            }
        }
        __syncthreads();

        for (int rr = 0; rr < 2; rr++) {
            int i = warp*2 + rr;
            float* wrow = wbuf + i*WROW;
            float* arow = arcs + i*WROW;
            float m = -INFINITY;
            for (int s = lane; s < 1024; s += 32) m = fmaxf(m, wrow[s]);
#pragma unroll
            for (int off = 16; off; off >>= 1) m = fmaxf(m, __shfl_xor_sync(0xffffffffu, m, off));
            float ssum = 0.f;
            for (int s = lane; s < 1024; s += 32) {
                float e = __expf(wrow[s] - m);
                wrow[s] = e;
                ssum += e;
            }
#pragma unroll
            for (int off = 16; off; off >>= 1) ssum += __shfl_xor_sync(0xffffffffu, ssum, off);
            float inv = 1.f / ssum;
            for (int s = lane; s < 1024; s += 32) {
                float wv = wrow[s] * inv;
                wrow[s] = wv;
                arow[s] = fmaxf(arow[s], wv);
            }
        }
        __syncthreads();

        const float* Vh = V + (size_t)((b*H_ + h)*S_) * D_;
        float4 oacc[4];
#pragma unroll
        for (int r = 0; r < 4; r++) oacc[r] = make_float4(0.f, 0.f, 0.f, 0.f);

        for (int c0 = 0; c0 < 4; c0++) {
            int s0 = c0 * 256;
            if (c0) __syncthreads();
#pragma unroll
            for (int j = 0; j < 16; j++) {
                int idx = t + 256*j;
                int row = idx >> 4, c4 = idx & 15;
                kvs4[row*17 + c4] = *(const float4*)&Vh[(s0+row)*64 + c4*4];
            }
            __syncthreads();
            int sl0 = oks * 64;
#pragma unroll 4
            for (int g = 0; g < 16; g++) {
                float wv[4][4];
#pragma unroll
                for (int r = 0; r < 4; r++) {
                    float4 w4 = *(const float4*)&wbuf[(oig*4+r)*WROW + s0 + sl0 + g*4];
                    wv[r][0] = w4.x; wv[r][1] = w4.y; wv[r][2] = w4.z; wv[r][3] = w4.w;
                }
#pragma unroll
                for (int j = 0; j < 4; j++) {
                    float4 v = kvs4[(sl0 + g*4 + j)*17 + odg];
#pragma unroll
                    for (int r = 0; r < 4; r++) {
                        oacc[r].x += wv[r][j]*v.x;
                        oacc[r].y += wv[r][j]*v.y;
                        oacc[r].z += wv[r][j]*v.z;
                        oacc[r].w += wv[r][j]*v.w;
                    }
                }
            }
        }
        __syncthreads();
        float4* red4 = (float4*)kvs;
#pragma unroll
        for (int r = 0; r < 4; r++) red4[t*4 + r] = oacc[r];
        __syncthreads();
        if (oks == 0) {
#pragma unroll
            for (int r = 0; r < 4; r++) {
                float4 o = oacc[r];
#pragma unroll
                for (int ks = 1; ks < 4; ks++) {
                    int peer = oig*64 + ks*16 + odg;
                    float4 p = red4[peer*4 + r];
                    o.x += p.x; o.y += p.y; o.z += p.z; o.w += p.w;
                }
                *(float4*)&attn_out[((t0 + oig*4 + r)*B_ + b)*E_ + h*D_ + odg*4] = o;
            }
        }
    }
    __syncthreads();

    float lsum = 0.f;
    for (int k = 0; k < 64; k++) {
        int idx = t + 256*k;
        int i = idx >> 10, s = idx & 1023;
        int rel = trel[(size_t)((t0+i)*B_ + b)*S_ + s];
        if (rel != 0) {
            float p = fminf(arcs[i*WROW + s], 1.0f);
            float term = (rel != 2) ? logf(p) : log1pf(-p);
            lsum -= fmaxf(term, -100.f);
        }
    }
    float* red = kvs;
    red[t] = lsum;
    __syncthreads();
    for (int off = 128; off; off >>= 1) {
        if (t < off) red[t] += red[t + off];
        __syncthreads();
    }
    if (t == 0) losspart[blockIdx.x * B_ + b] = red[0];
}

// ---------------- deterministic loss finalize ----------------
__global__ void finalize_kernel(const float* __restrict__ lp,
                                const float* __restrict__ strat,
                                float* __restrict__ out)
{
    int b = threadIdx.x;
    if (b < B_) {
        float s = 0.f;
        for (int k = 0; k < NTILES; k++) s += lp[k*B_ + b];
        out[b] = s * strat[b];
    }
}

// ---------------- launch ----------------
extern "C" void kernel_launch(void* const* d_in, const int* in_sizes, int n_in,
                              void* d_out, int out_size)
{
    const float* outs = nullptr; const float* gstate = nullptr;
    const unsigned char* pmask = nullptr; const float* amask = nullptr;
    const float* strat = nullptr; const int* trel = nullptr;
    const float* Win = nullptr; const float* b_in = nullptr;
    const float* Wout = nullptr; const float* b_out = nullptr;
    for (int i = 0; i < n_in; i++) {
        long n = in_sizes[i];
        if (n == (long)T_*B_*E_) { if (!outs) outs = (const float*)d_in[i]; else if (!gstate) gstate = (const float*)d_in[i]; }
        else if (n == (long)B_*S_)      pmask = (const unsigned char*)d_in[i];
        else if (n == (long)T_*S_)      amask = (const float*)d_in[i];
        else if (n == (long)B_)         strat = (const float*)d_in[i];
        else if (n == (long)T_*B_*S_)   trel  = (const int*)d_in[i];
        else if (n == (long)3*E_*E_)    Win   = (const float*)d_in[i];
        else if (n == (long)3*E_)       b_in  = (const float*)d_in[i];
        else if (n == (long)E_*E_)      Wout  = (const float*)d_in[i];
        else if (n == (long)E_)         b_out = (const float*)d_in[i];
    }
    float* out = (float*)d_out;

    float *Qp, *Kp, *Vp, *Ap, *Lp;
    __nv_bfloat16 *oh, *ol, *gh, *gl, *th, *tl, *Wh, *Wl;
    cudaGetSymbolAddress((void**)&Qp, g_Q);
    cudaGetSymbolAddress((void**)&Kp, g_K);
    cudaGetSymbolAddress((void**)&Vp, g_V);
    cudaGetSymbolAddress((void**)&Ap, g_attn);
    cudaGetSymbolAddress((void**)&Lp, g_losspart);
    cudaGetSymbolAddress((void**)&oh, g_oh); cudaGetSymbolAddress((void**)&ol, g_ol);
    cudaGetSymbolAddress((void**)&gh, g_gh); cudaGetSymbolAddress((void**)&gl, g_gl);
    cudaGetSymbolAddress((void**)&th, g_th); cudaGetSymbolAddress((void**)&tl, g_tl);
    cudaGetSymbolAddress((void**)&Wh, g_Wh); cudaGetSymbolAddress((void**)&Wl, g_Wl);

    // outs passthrough (output layout: [arc_loss(8) | outs(T*B*E) | x(T*B*E)])
    cudaMemcpyAsync(out + B_, outs, sizeof(float)*(size_t)T_*B_*E_,
                    cudaMemcpyDeviceToDevice);

    const int GM_SMEM = 2 * STAGE_ELEMS * 2;   // 61440 B
    cudaFuncSetAttribute(mma_gemm, cudaFuncAttributeMaxDynamicSharedMemorySize, GM_SMEM);

    // split conversions
    int nact4 = T_*B_*E_/4;
    cvt_split<<<(nact4+255)/256, 256>>>(outs,   oh, ol, nact4);
    cvt_split<<<(nact4+255)/256, 256>>>(gstate, gh, gl, nact4);
    int nwin4 = 3*E_*E_/4, nwout4 = E_*E_/4;
    cvt_split<<<(nwin4+255)/256, 256>>>(Win,  Wh, Wl, nwin4);
    cvt_split<<<(nwout4+255)/256, 256>>>(Wout, Wh + 3*E_*E_, Wl + 3*E_*E_, nwout4);

    dim3 gg(64, 12);
    mma_gemm<<<gg, 256, GM_SMEM>>>(oh, ol, Wh,            Wl,            b_in,        Qp, 0.125f, 0);
    mma_gemm<<<gg, 256, GM_SMEM>>>(gh, gl, Wh +   E_*E_,  Wl +   E_*E_,  b_in +   E_, Kp, 1.0f,   1);
    mma_gemm<<<gg, 256, GM_SMEM>>>(gh, gl, Wh + 2*E_*E_,  Wl + 2*E_*E_,  b_in + 2*E_, Vp, 1.0f,   1);

    const int ATTN_SMEM = (256*68 + 16*WROW + 16*WROW + 16*68) * 4;  // 205568 B
    cudaFuncSetAttribute(attn_kernel, cudaFuncAttributeMaxDynamicSharedMemorySize, ATTN_SMEM);
    attn_kernel<<<dim3(NTILES, B_), 256, ATTN_SMEM>>>(Qp, Kp, Vp, amask, pmask, trel, Ap, Lp);

    cvt_split<<<(nact4+255)/256, 256>>>(Ap, th, tl, nact4);
    mma_gemm<<<gg, 256, GM_SMEM>>>(th, tl, Wh + 3*E_*E_, Wl + 3*E_*E_, b_out,
                                   out + B_ + (size_t)T_*B_*E_, 1.0f, 0);

    finalize_kernel<<<1, 32>>>(Lp, strat, out);
}